// round 14
// baseline (speedup 1.0000x reference)
#include <cuda_runtime.h>
#include <cuda_bf16.h>

// TransferMatrixMethod: B=256, L=64 (62 interior), W=512.
// R11 structure (best: 8.86us) + critical-path LDS removal:
//   (1) {n,n} and {mr,mr} merged into one ulonglong2 -> 1 LDS.128/layer
//   (2) layer constants prefetched depth-1 alongside the trig, so the
//       29-cycle LDS latency is off the accumulator critical path
//   (3) nd packed as float2 per layer-pair -> 1 LDS.64 per 2 layers
//
// Layer matrices [[a, ib],[ic, d]] closed under multiplication; track
// A,B,C,Dt(=-D), f32x2 lanes = 2 adjacent wavelengths. 2-way layer split
// (lid<16: layers 0..30, lid>=16: layers 31..61), combine via shuffle
// xor 16 (verified R4/R11). launch_bounds(128,7): grid 1024 resident in
// one wave, ~70-reg budget.

#define NLAYERS 62
#define HALF_L  31
#define LTOT    64
#define WDIM    512
#define TPB     128

typedef unsigned long long u64;

__device__ __forceinline__ u64 pack2(float lo, float hi) {
    u64 r;
    asm("mov.b64 %0, {%1, %2};" : "=l"(r) : "f"(lo), "f"(hi));
    return r;
}
__device__ __forceinline__ void unpack2(float& lo, float& hi, u64 v) {
    asm("mov.b64 {%0, %1}, %2;" : "=f"(lo), "=f"(hi) : "l"(v));
}
__device__ __forceinline__ u64 mul2(u64 a, u64 b) {
    u64 r;
    asm("mul.rn.f32x2 %0, %1, %2;" : "=l"(r) : "l"(a), "l"(b));
    return r;
}
__device__ __forceinline__ u64 fma2(u64 a, u64 b, u64 c) {
    u64 r;
    asm("fma.rn.f32x2 %0, %1, %2, %3;" : "=l"(r) : "l"(a), "l"(b), "l"(c));
    return r;
}
__device__ __forceinline__ u64 neg2(u64 a) {
    return a ^ 0x8000000080000000ULL;
}

__global__ __launch_bounds__(TPB, 7)
void tmm_kernel(const float* __restrict__ n_layers,
                const float* __restrict__ d_layers,
                const float* __restrict__ wavelengths,
                float* __restrict__ out)
{
    const int b   = blockIdx.x >> 2;            // 0..255
    const int q   = blockIdx.x & 3;             // quarter of wavelength axis
    const int t   = threadIdx.x;                // 0..127
    const int lid = t & 31;
    const int wrp = t >> 5;                     // warp in block, 0..3
    const int half  = lid >> 4;                 // 0: layers 0..30, 1: 31..61
    const int chain = wrp * 16 + (lid & 15);    // 0..63 within block
    const int w0    = (q * 64 + chain) * 2;     // even wavelength index

    // layer tables (each half uses indices [base, base+31); pads for prefetch)
    // s_nmr[l] = { {n,n}, {mr,mr} }  -> one LDS.128
    // s_ndp[p] = { nd(2p), nd(2p+1) } -> one LDS.64 per layer pair
    __shared__ ulonglong2 s_nmr[NLAYERS + 2];
    __shared__ float2     s_ndp[HALF_L + 1 + 1];  // 32 pairs cover 64 slots
    __shared__ float      s_nin, s_nsub;

    const float* nrow = n_layers + b * LTOT;
    const float* drow = d_layers + b * LTOT;

    if (t < NLAYERS + 2) {
        float nv = 1.0f, dv = 0.0f, mr = -1.0f;
        if (t < NLAYERS) {
            nv = nrow[t + 1];
            dv = drow[t + 1];
            mr = -1.0f / (nv + 1e-8f);
        }
        s_nmr[t] = make_ulonglong2(pack2(nv, nv), pack2(mr, mr));
        // nd table: pair p holds layers 2p, 2p+1 (identity nd=0 beyond 61)
        if ((t & 1) == 0) {
            const int l0 = t, l1 = t + 1;
            float nd0 = 0.0f, nd1 = 0.0f;
            if (l0 < NLAYERS) {
                float n0 = nrow[l0 + 1];
                nd0 = n0 * drow[l0 + 1];
            }
            if (l1 < NLAYERS) {
                float n1 = nrow[l1 + 1];
                nd1 = n1 * drow[l1 + 1];
            }
            s_ndp[t >> 1] = make_float2(nd0, nd1);
        }
    }
    if (t == NLAYERS + 2) s_nin  = nrow[0];
    if (t == NLAYERS + 3) s_nsub = nrow[LTOT - 1];
    __syncthreads();

    const float TWO_PI = 6.28318530717958647692f;
    const float2 lam = *reinterpret_cast<const float2*>(wavelengths + w0);
    const float k0 = __fdividef(TWO_PI, lam.x);
    const float k1 = __fdividef(TWO_PI, lam.y);

    const int base = half * HALF_L;   // 0 or 31

    u64 A  = pack2(1.0f, 1.0f);
    u64 Bv = pack2(0.0f, 0.0f);
    u64 C  = pack2(0.0f, 0.0f);
    u64 Dt = pack2(-1.0f, -1.0f);   // -D

    // prologue: constants + trig for l = 0 of this half.
    // nd for global layer (base + l): pair index (base+l)>>1, elem (base+l)&1.
    // base is 0 or 31 -> parity of (base+l) = (l^half)&1 at compile time
    // per iteration since the loop is fully unrolled.
    ulonglong2 nmr = s_nmr[base];
    float s0, c0, s1, c1;
    {
        const float2 p = s_ndp[base >> 1];
        const float nd = (base & 1) ? p.y : p.x;
        __sincosf(nd * k0, &s0, &c0);
        __sincosf(nd * k1, &s1, &c1);
    }

    #pragma unroll
    for (int l = 0; l < HALF_L; ++l) {
        const u64 sp2 = pack2(s0, s1);
        const u64 cp2 = pack2(c0, c1);
        const u64 n2  = nmr.x;
        const u64 mr2 = nmr.y;

        // ---- depth-1 prefetch: constants + trig for layer l+1 ----
        {
            const int gl = base + l + 1;           // compile-time per iter
            nmr = s_nmr[gl];
            const float2 p = s_ndp[gl >> 1];
            const float nd = (gl & 1) ? p.y : p.x;
            __sincosf(nd * k0, &s0, &c0);
            __sincosf(nd * k1, &s1, &c1);
        }

        // ---- matrix update for layer l (R4/R11 verbatim algebra) ----
        const u64 ns2  = mul2(sp2, n2);    // { n*sin }
        const u64 msr2 = mul2(sp2, mr2);   // { -sin/(n+eps) }

        u64 nA = fma2(ns2,  Bv, mul2(cp2, A));
        u64 nB = fma2(msr2, A,  mul2(cp2, Bv));
        u64 nC = fma2(ns2,  Dt, mul2(cp2, C));
        u64 nD = fma2(msr2, C,  mul2(cp2, Dt));
        A = nA; Bv = nB; C = nC; Dt = nD;
    }

    // exchange halves: lane i <-> lane i^16 (verified R4/R11)
    const unsigned FULL = 0xffffffffu;
    u64 Ay  = __shfl_xor_sync(FULL, A,  16);
    u64 By  = __shfl_xor_sync(FULL, Bv, 16);
    u64 Cy  = __shfl_xor_sync(FULL, C,  16);
    u64 Dty = __shfl_xor_sync(FULL, Dt, 16);

    if (half == 0) {
        // combine: M = X * Y   (X = own = layers 1..31, Y = partner)
        u64 Dy = neg2(Dty);
        u64 fA = fma2(neg2(Bv), Cy, mul2(A, Ay));        // Ax*Ay - Bx*Cy
        u64 fB = fma2(Bv, Dy,       mul2(A, By));        // Ax*By + Bx*Dy
        u64 fC = fma2(neg2(Dt), Cy, mul2(C, Ay));        // Cx*Ay + Dx*Cy
        u64 fD = fma2(neg2(C),  By, mul2(neg2(Dt), Dy)); // Dx*Dy - Cx*By

        float A0, A1, B0, B1, C0, C1, D0, D1;
        unpack2(A0, A1, fA);
        unpack2(B0, B1, fB);
        unpack2(C0, C1, fC);
        unpack2(D0, D1, fD);

        const float nin  = s_nin;
        const float nsub = s_nsub;

        float R[2];
        #pragma unroll
        for (int i = 0; i < 2; ++i) {
            const float a  = i ? A1 : A0;
            const float bb = i ? B1 : B0;
            const float c  = i ? C1 : C0;
            const float d  = i ? D1 : D0;

            const float Er = a + 1e-9f;
            const float Ei = bb * nsub;
            const float Hr = d * nsub;
            const float Hi = c;

            const float numr = fmaf(nin, Er, -Hr);
            const float numi = fmaf(nin, Ei, -Hi);
            const float denr = fmaf(nin, Er,  Hr);
            const float deni = fmaf(nin, Ei,  Hi);

            const float num2 = fmaf(numr, numr, numi * numi);
            const float den2 = fmaf(denr, denr, deni * deni);
            R[i] = num2 / den2;
        }

        *reinterpret_cast<float2*>(out + b * WDIM + w0) = make_float2(R[0], R[1]);
    }
}

extern "C" void kernel_launch(void* const* d_in, const int* in_sizes, int n_in,
                              void* d_out, int out_size)
{
    const float* n_layers    = (const float*)d_in[0];  // (256, 64)
    const float* d_layers    = (const float*)d_in[1];  // (256, 64)
    const float* wavelengths = (const float*)d_in[2];  // (512,)
    float* out = (float*)d_out;                        // (256, 512)

    tmm_kernel<<<1024, TPB>>>(n_layers, d_layers, wavelengths, out);
}